// round 2
// baseline (speedup 1.0000x reference)
#include <cuda_runtime.h>
#include <cstdint>

// Problem constants
#define BB 512
#define TT 1024
#define DD 64
#define HH 128
#define GG 384   // 3*H
#define NTHR 768 // gru kernel threads: (g, half) split-K

// Scratch for precomputed input gates, layout [t][b][g]
__device__ float g_xg[(size_t)TT * BB * GG];

// ---------- packed fp32x2 helpers (PTX-only; ptxas won't auto-fuse) ----------
__device__ __forceinline__ unsigned long long ffma2(unsigned long long a,
                                                    unsigned long long b,
                                                    unsigned long long c) {
    unsigned long long d;
    asm("fma.rn.f32x2 %0, %1, %2, %3;" : "=l"(d) : "l"(a), "l"(b), "l"(c));
    return d;
}
__device__ __forceinline__ float f2sum(unsigned long long v) {
    float lo, hi;
    asm("mov.b64 {%0, %1}, %2;" : "=f"(lo), "=f"(hi) : "l"(v));
    return lo + hi;
}
__device__ __forceinline__ float sigmoidf_(float x) {
    return __fdividef(1.0f, 1.0f + __expf(-x));
}

// ============================================================================
// Kernel 1: xg[t][b][g] = b_ih[g] + sum_d x[b][t][d] * w_ih[g][d]
// ============================================================================
__global__ void __launch_bounds__(GG) xg_kernel(const float* __restrict__ x,
                                                const float* __restrict__ w_ih,
                                                const float* __restrict__ b_ih) {
    __shared__ __align__(16) float xs[128 * DD];  // 32 KB

    const int t  = blockIdx.x >> 2;
    const int b0 = (blockIdx.x & 3) * 128;
    const int g  = threadIdx.x;

    const float4* x4 = reinterpret_cast<const float4*>(x);
    float4* xs4 = reinterpret_cast<float4*>(xs);
    for (int i = threadIdx.x; i < 128 * 16; i += GG) {
        int row = i >> 4, c4 = i & 15;
        xs4[i] = x4[((size_t)(b0 + row) * TT + t) * 16 + c4];
    }

    unsigned long long wq[32];
    const unsigned long long* wp =
        reinterpret_cast<const unsigned long long*>(w_ih + (size_t)g * DD);
#pragma unroll
    for (int i = 0; i < 32; i++) wq[i] = wp[i];
    const unsigned long long accInit =
        (unsigned long long)__float_as_uint(b_ih[g]);  // (bias, 0)

    __syncthreads();

    float* outp = g_xg + ((size_t)t * BB + b0) * GG + g;
    for (int row = 0; row < 128; row += 2) {
        const ulonglong2* hx0 =
            reinterpret_cast<const ulonglong2*>(xs + row * DD);
        const ulonglong2* hx1 =
            reinterpret_cast<const ulonglong2*>(xs + (row + 1) * DD);
        unsigned long long acc0 = accInit, acc1 = accInit;
#pragma unroll
        for (int i = 0; i < 16; i++) {
            ulonglong2 v0 = hx0[i];  // broadcast LDS.128
            acc0 = ffma2(wq[2 * i], v0.x, acc0);
            acc0 = ffma2(wq[2 * i + 1], v0.y, acc0);
            ulonglong2 v1 = hx1[i];
            acc1 = ffma2(wq[2 * i], v1.x, acc1);
            acc1 = ffma2(wq[2 * i + 1], v1.y, acc1);
        }
        outp[(size_t)row * GG]       = f2sum(acc0);
        outp[(size_t)(row + 1) * GG] = f2sum(acc1);
    }
}

// ============================================================================
// Kernel 2: persistent GRU recurrence, split-K.
// 128 CTAs x 4 batch rows, 768 threads. Thread (g, half) owns w_hh[g][half*64..+64]
// in 32 f32x2 regs (~80 regs total -> no spills). Partials combined via smem.
// ============================================================================
__global__ void __launch_bounds__(NTHR, 1)
gru_kernel(const float* __restrict__ mask,
           const float* __restrict__ w_hh,
           const float* __restrict__ b_hh,
           const float* __restrict__ Wo,
           const float* __restrict__ bo,
           float* __restrict__ out) {
    __shared__ __align__(16) float h_s[4][HH];      // 2 KB
    __shared__ float P_s[2][4][GG];                 // 12 KB partial dots
    __shared__ float m_s[4];
    __shared__ float wo_s[2][HH];

    const int tid  = threadIdx.x;
    const int half = tid / GG;          // warp-uniform (GG = 12 warps)
    const int g    = tid - half * GG;
    const int b0   = blockIdx.x * 4;

    for (int i = tid; i < 4 * HH; i += NTHR) (&h_s[0][0])[i] = 0.0f;
    for (int i = tid; i < 2 * HH; i += NTHR) (&wo_s[0][0])[i] = Wo[i];

    // this thread's half-row of w_hh -> 32 packed pairs (64 regs)
    unsigned long long wq[32];
    const unsigned long long* wp = reinterpret_cast<const unsigned long long*>(
        w_hh + (size_t)g * HH + half * 64);
#pragma unroll
    for (int i = 0; i < 32; i++) wq[i] = wp[i];
    // bias contributed once, by half 0 only
    const unsigned long long accInit =
        half ? 0ull : (unsigned long long)__float_as_uint(b_hh[g]);

    // gate-phase cell assignment (tid < 512): cell (cb, cj)
    const int cb = (tid >> 7) & 3;
    const int cj = tid & 127;
    const bool is_cell = tid < 512;

    const float* xg_cell = g_xg + ((size_t)(b0 + cb)) * GG + cj; // step 0
    const float* mp = mask + (size_t)(b0 + (tid & 3)) * TT;
    const float bo0 = bo[0], bo1 = bo[1];

    __syncthreads();

    for (int t = 0; t < TT; t++) {
        // ---- prefetch xg (gate-phase regs) + mask; hidden under matvec ----
        float xr_v = 0.f, xz_v = 0.f, xn_v = 0.f;
        if (is_cell) {
            xr_v = xg_cell[0];
            xz_v = xg_cell[HH];
            xn_v = xg_cell[2 * HH];
        }
        if (tid < 4) m_s[tid] = mp[t];

        // ---- half matvec: P[half][b][g] = (bias?) + h[b][half*64..] . wq ----
        const float* hbase = &h_s[0][0] + half * 64;
        {
            unsigned long long a0 = accInit, a1 = accInit;
            const ulonglong2* h0p = reinterpret_cast<const ulonglong2*>(hbase);
            const ulonglong2* h1p = reinterpret_cast<const ulonglong2*>(hbase + HH);
#pragma unroll
            for (int i = 0; i < 16; i++) {
                ulonglong2 v0 = h0p[i];
                a0 = ffma2(wq[2 * i], v0.x, a0);
                a0 = ffma2(wq[2 * i + 1], v0.y, a0);
                ulonglong2 v1 = h1p[i];
                a1 = ffma2(wq[2 * i], v1.x, a1);
                a1 = ffma2(wq[2 * i + 1], v1.y, a1);
            }
            P_s[half][0][g] = f2sum(a0);
            P_s[half][1][g] = f2sum(a1);
        }
        {
            unsigned long long a2 = accInit, a3 = accInit;
            const ulonglong2* h2p = reinterpret_cast<const ulonglong2*>(hbase + 2 * HH);
            const ulonglong2* h3p = reinterpret_cast<const ulonglong2*>(hbase + 3 * HH);
#pragma unroll
            for (int i = 0; i < 16; i++) {
                ulonglong2 v2 = h2p[i];
                a2 = ffma2(wq[2 * i], v2.x, a2);
                a2 = ffma2(wq[2 * i + 1], v2.y, a2);
                ulonglong2 v3 = h3p[i];
                a3 = ffma2(wq[2 * i], v3.x, a3);
                a3 = ffma2(wq[2 * i + 1], v3.y, a3);
            }
            P_s[half][2][g] = f2sum(a2);
            P_s[half][3][g] = f2sum(a3);
        }
        __syncthreads();

        // ---- gate phase: 512 cells, one per thread ----
        if (is_cell) {
            float hr = P_s[0][cb][cj]        + P_s[1][cb][cj];
            float hz = P_s[0][cb][cj + HH]   + P_s[1][cb][cj + HH];
            float hn = P_s[0][cb][cj + 2*HH] + P_s[1][cb][cj + 2*HH];
            float r  = sigmoidf_(xr_v + hr);
            float z  = sigmoidf_(xz_v + hz);
            float n  = tanhf(fmaf(r, hn, xn_v));
            float ho = h_s[cb][cj];
            float hnew = fmaf(z, ho - n, n);        // (1-z)*n + z*ho
            float m  = m_s[cb];
            h_s[cb][cj] = fmaf(m, hnew - ho, ho);   // m*hnew + (1-m)*ho
        }
        __syncthreads();

        // ---- logits: 8 warps, one per (b, o); warp-reduce 128-dot ----
        if (tid < 256) {
            int w = tid >> 5, lane = tid & 31;
            int b = w >> 1, o = w & 1;
            float p = 0.0f;
#pragma unroll
            for (int q = 0; q < 4; q++)
                p = fmaf(h_s[b][lane + 32 * q], wo_s[o][lane + 32 * q], p);
#pragma unroll
            for (int off = 16; off; off >>= 1)
                p += __shfl_down_sync(0xffffffffu, p, off);
            if (lane == 0)
                out[(((size_t)(b0 + b)) * TT + t) * 2 + o] = p + (o ? bo1 : bo0);
        }

        xg_cell += (size_t)BB * GG;
    }
}

// ============================================================================
extern "C" void kernel_launch(void* const* d_in, const int* in_sizes, int n_in,
                              void* d_out, int out_size) {
    const float* x    = (const float*)d_in[0];
    const float* mask = (const float*)d_in[1];
    const float* w_ih = (const float*)d_in[2];
    const float* w_hh = (const float*)d_in[3];
    const float* b_ih = (const float*)d_in[4];
    const float* b_hh = (const float*)d_in[5];
    const float* Wo   = (const float*)d_in[6];
    const float* bo   = (const float*)d_in[7];
    float* out = (float*)d_out;

    xg_kernel<<<TT * 4, GG>>>(x, w_ih, b_ih);
    gru_kernel<<<BB / 4, NTHR>>>(mask, w_hh, b_hh, Wo, bo, out);
}